// round 2
// baseline (speedup 1.0000x reference)
#include <cuda_runtime.h>

// LIF membrane update, restructured to kill the w L2 double-traffic:
//   K1: grid = n-tiles(4) x i-slices(16) x b-groups(16). Each block stages its
//       w slice [64 x 32 float4] in SMEM (32KB) once, then each of 8 warps
//       streams x for ONE batch against the smem w -> partial sum to scratch.
//   K2: reduce 16 partials, apply LIF epilogue, write v_new ++ z_new.
// Shapes: x[128,1024,512], w[1024,512], v[128,512], z[128,512]

#define B_      128
#define N_IN_   1024
#define NN_     512
#define NN4_    (NN_ / 4)          // 128 float4 per n-row
#define ALPHA_  0.995f
#define V_TH_   2.0f

#define NTILES   4                 // 4 x 32 float4 = 128 float4 = 512 n
#define NTILE4   32                // float4 per n-tile (one warp-width)
#define ISLICES  16
#define IPER     (N_IN_ / ISLICES) // 64 i per slice
#define BGROUPS  16
#define BPER     (B_ / BGROUPS)    // 8 batches per block (1 per warp)
#define THREADS  256

// Partial sums: [ISLICES][B][NN4] float4 = 4 MB (L2-resident)
__device__ float4 g_partial[ISLICES * B_ * NN4_];

__global__ __launch_bounds__(THREADS)
void lif_partial_kernel(const float4* __restrict__ x,
                        const float4* __restrict__ w)
{
    __shared__ float4 wsm[IPER][NTILE4];   // 32 KB

    const int bx = blockIdx.x;
    const int nt = bx & (NTILES - 1);            // n-tile
    const int sl = (bx >> 2) & (ISLICES - 1);    // i-slice
    const int bg = bx >> 6;                      // b-group

    const int lane = threadIdx.x & 31;           // n4 within tile
    const int wid  = threadIdx.x >> 5;           // warp -> batch within group

    const int i0 = sl * IPER;
    const int n4 = nt * NTILE4 + lane;

    // Cooperative w-slice load: 64 rows x 32 float4, 256 threads x 8 each
    {
        const float4* wsrc = w + (size_t)i0 * NN4_ + nt * NTILE4;
        #pragma unroll
        for (int t = threadIdx.x; t < IPER * NTILE4; t += THREADS) {
            int i = t >> 5, l = t & 31;
            wsm[i][l] = __ldg(&wsrc[(size_t)i * NN4_ + l]);
        }
    }
    __syncthreads();

    const int b = bg * BPER + wid;
    const float4* xb = x + ((size_t)b * N_IN_ + i0) * NN4_ + n4;

    float4 acc = make_float4(0.f, 0.f, 0.f, 0.f);
    #pragma unroll 8
    for (int i = 0; i < IPER; ++i) {
        float4 xv = __ldcs(&xb[(size_t)i * NN4_]);   // pure DRAM stream
        float4 wv = wsm[i][lane];                    // smem, conflict-free
        acc.x += xv.x * wv.x;
        acc.y += xv.y * wv.y;
        acc.z += xv.z * wv.z;
        acc.w += xv.w * wv.w;
    }

    g_partial[((size_t)sl * B_ + b) * NN4_ + n4] = acc;
}

__global__ __launch_bounds__(256)
void lif_epilogue_kernel(const float4* __restrict__ v,
                         const float4* __restrict__ z,
                         float4* __restrict__ out)
{
    const int t = blockIdx.x * 256 + threadIdx.x;   // (b, n4) over 128*128
    if (t >= B_ * NN4_) return;

    float4 sum = make_float4(0.f, 0.f, 0.f, 0.f);
    #pragma unroll
    for (int sl = 0; sl < ISLICES; ++sl) {
        float4 p = g_partial[(size_t)sl * B_ * NN4_ + t];
        sum.x += p.x; sum.y += p.y; sum.z += p.z; sum.w += p.w;
    }

    float4 vv = v[t];
    float4 zz = z[t];

    float4 vn;
    vn.x = ALPHA_ * vv.x + sum.x - V_TH_ * zz.x;
    vn.y = ALPHA_ * vv.y + sum.y - V_TH_ * zz.y;
    vn.z = ALPHA_ * vv.z + sum.z - V_TH_ * zz.z;
    vn.w = ALPHA_ * vv.w + sum.w - V_TH_ * zz.w;

    float4 zn;
    zn.x = (vn.x - V_TH_ > 0.f) ? 1.f : 0.f;
    zn.y = (vn.y - V_TH_ > 0.f) ? 1.f : 0.f;
    zn.z = (vn.z - V_TH_ > 0.f) ? 1.f : 0.f;
    zn.w = (vn.w - V_TH_ > 0.f) ? 1.f : 0.f;

    out[t] = vn;                  // v_new: first B*NN floats
    out[B_ * NN4_ + t] = zn;      // z_new: next  B*NN floats
}

extern "C" void kernel_launch(void* const* d_in, const int* in_sizes, int n_in,
                              void* d_out, int out_size)
{
    const float4* x = (const float4*)d_in[0];  // [128,1024,512] f32
    const float4* w = (const float4*)d_in[1];  // [1024,512]     f32
    const float4* v = (const float4*)d_in[2];  // [128,512]      f32
    const float4* z = (const float4*)d_in[3];  // [128,512]      f32
    float4* out = (float4*)d_out;              // [2,128,512]    f32

    (void)in_sizes; (void)n_in; (void)out_size;

    lif_partial_kernel<<<NTILES * ISLICES * BGROUPS, THREADS>>>(x, w);
    lif_epilogue_kernel<<<(B_ * NN4_ + 255) / 256, 256>>>(v, z, out);
}

// round 3
// speedup vs baseline: 1.2511x; 1.2511x over previous
#include <cuda_runtime.h>

// LIF membrane update, single kernel:
//   v_new[b,n] = ALPHA*v[b,n] + sum_i x[b,i,n]*w[i,n] - V_TH*z[b,n]
//   z_new[b,n] = (v_new[b,n] - V_TH > 0) ? 1 : 0
// Shapes: x[128,1024,512], w[1024,512], v[128,512], z[128,512]
// HBM-bound (x = 256 MB streamed once). This version targets latency hiding:
// 16 warps/block (i-sliced) + explicit 4-row load batching for MLP>=4.

#define B_     128
#define N_IN_  1024
#define NN_    512
#define NN4_   (NN_ / 4)          // 128 float4 per n-row
#define ALPHA_ 0.995f
#define V_TH_  2.0f

#define WARPS   16
#define IPER    (N_IN_ / WARPS)   // 64 i-rows per warp
#define THREADS (WARPS * 32)      // 512

__global__ __launch_bounds__(THREADS, 2)
void lif_kernel(const float4* __restrict__ x,
                const float4* __restrict__ w,
                const float4* __restrict__ v,
                const float4* __restrict__ z,
                float4* __restrict__ out)
{
    __shared__ float4 red[WARPS][32];   // 8 KB

    const int b    = blockIdx.x >> 2;        // 4 n-tiles per batch
    const int nt   = blockIdx.x & 3;
    const int lane = threadIdx.x & 31;
    const int wid  = threadIdx.x >> 5;       // warp -> i-slice
    const int n4   = nt * 32 + lane;         // float4 index in n

    const float4* xb = x + ((size_t)b * N_IN_ + wid * IPER) * NN4_ + n4;
    const float4* wb = w + (size_t)(wid * IPER) * NN4_ + n4;

    float4 acc = make_float4(0.f, 0.f, 0.f, 0.f);

    for (int i = 0; i < IPER; i += 4) {
        // batch the 8 independent loads so they issue back-to-back (MLP=8)
        float4 x0 = __ldcs(&xb[(size_t)(i + 0) * NN4_]);
        float4 x1 = __ldcs(&xb[(size_t)(i + 1) * NN4_]);
        float4 x2 = __ldcs(&xb[(size_t)(i + 2) * NN4_]);
        float4 x3 = __ldcs(&xb[(size_t)(i + 3) * NN4_]);
        float4 w0 = __ldg (&wb[(size_t)(i + 0) * NN4_]);
        float4 w1 = __ldg (&wb[(size_t)(i + 1) * NN4_]);
        float4 w2 = __ldg (&wb[(size_t)(i + 2) * NN4_]);
        float4 w3 = __ldg (&wb[(size_t)(i + 3) * NN4_]);

        acc.x += x0.x * w0.x; acc.y += x0.y * w0.y;
        acc.z += x0.z * w0.z; acc.w += x0.w * w0.w;
        acc.x += x1.x * w1.x; acc.y += x1.y * w1.y;
        acc.z += x1.z * w1.z; acc.w += x1.w * w1.w;
        acc.x += x2.x * w2.x; acc.y += x2.y * w2.y;
        acc.z += x2.z * w2.z; acc.w += x2.w * w2.w;
        acc.x += x3.x * w3.x; acc.y += x3.y * w3.y;
        acc.z += x3.z * w3.z; acc.w += x3.w * w3.w;
    }

    red[wid][lane] = acc;
    __syncthreads();

    if (threadIdx.x < 32) {
        float4 sum = red[0][lane];
        #pragma unroll
        for (int k = 1; k < WARPS; ++k) {
            float4 t = red[k][lane];
            sum.x += t.x; sum.y += t.y; sum.z += t.z; sum.w += t.w;
        }

        const int on = b * NN4_ + n4;
        float4 vv = v[on];
        float4 zz = z[on];

        float4 vn;
        vn.x = ALPHA_ * vv.x + sum.x - V_TH_ * zz.x;
        vn.y = ALPHA_ * vv.y + sum.y - V_TH_ * zz.y;
        vn.z = ALPHA_ * vv.z + sum.z - V_TH_ * zz.z;
        vn.w = ALPHA_ * vv.w + sum.w - V_TH_ * zz.w;

        float4 zn;
        zn.x = (vn.x - V_TH_ > 0.f) ? 1.f : 0.f;
        zn.y = (vn.y - V_TH_ > 0.f) ? 1.f : 0.f;
        zn.z = (vn.z - V_TH_ > 0.f) ? 1.f : 0.f;
        zn.w = (vn.w - V_TH_ > 0.f) ? 1.f : 0.f;

        out[on] = vn;                  // v_new: first B*NN floats
        out[B_ * NN4_ + on] = zn;      // z_new: next B*NN floats
    }
}

extern "C" void kernel_launch(void* const* d_in, const int* in_sizes, int n_in,
                              void* d_out, int out_size)
{
    const float4* x = (const float4*)d_in[0];  // [128,1024,512] f32
    const float4* w = (const float4*)d_in[1];  // [1024,512]     f32
    const float4* v = (const float4*)d_in[2];  // [128,512]      f32
    const float4* z = (const float4*)d_in[3];  // [128,512]      f32
    float4* out = (float4*)d_out;              // [2,128,512]    f32

    (void)in_sizes; (void)n_in; (void)out_size;

    lif_kernel<<<B_ * 4, THREADS>>>(x, w, v, z, out);
}

// round 4
// speedup vs baseline: 1.3055x; 1.0434x over previous
#include <cuda_runtime.h>

// LIF membrane update, single kernel, single-wave grid:
//   v_new[b,n] = ALPHA*v[b,n] + sum_i x[b,i,n]*w[i,n] - V_TH*z[b,n]
//   z_new[b,n] = (v_new[b,n] - V_TH > 0) ? 1 : 0
// Shapes: x[128,1024,512], w[1024,512], v[128,512], z[128,512]
// 512 blocks x 256 threads, __launch_bounds__(256,4) => all CTAs resident
// in one wave (592 slots on 148 SMs) -> no tail. Explicit 4-row load
// batching keeps 4 independent DRAM loads in flight per warp.

#define B_     128
#define N_IN_  1024
#define NN_    512
#define NN4_   (NN_ / 4)          // 128 float4 per n-row
#define ALPHA_ 0.995f
#define V_TH_  2.0f

#define WARPS   8
#define IPER    (N_IN_ / WARPS)   // 128 i-rows per warp
#define THREADS (WARPS * 32)      // 256

__global__ __launch_bounds__(THREADS, 4)
void lif_kernel(const float4* __restrict__ x,
                const float4* __restrict__ w,
                const float4* __restrict__ v,
                const float4* __restrict__ z,
                float4* __restrict__ out)
{
    __shared__ float4 red[WARPS][32];   // 4 KB

    const int b    = blockIdx.x >> 2;        // 4 n-tiles per batch
    const int nt   = blockIdx.x & 3;
    const int lane = threadIdx.x & 31;
    const int wid  = threadIdx.x >> 5;       // warp -> i-slice
    const int n4   = nt * 32 + lane;         // float4 index in n

    const float4* xb = x + ((size_t)b * N_IN_ + wid * IPER) * NN4_ + n4;
    const float4* wb = w + (size_t)(wid * IPER) * NN4_ + n4;

    float4 acc = make_float4(0.f, 0.f, 0.f, 0.f);

    for (int i = 0; i < IPER; i += 4) {
        // 4 independent DRAM loads first, then 4 L2 loads: MLP=8 per warp-iter
        float4 x0 = __ldcs(&xb[(size_t)(i + 0) * NN4_]);
        float4 x1 = __ldcs(&xb[(size_t)(i + 1) * NN4_]);
        float4 x2 = __ldcs(&xb[(size_t)(i + 2) * NN4_]);
        float4 x3 = __ldcs(&xb[(size_t)(i + 3) * NN4_]);
        float4 w0 = __ldg (&wb[(size_t)(i + 0) * NN4_]);
        float4 w1 = __ldg (&wb[(size_t)(i + 1) * NN4_]);
        float4 w2 = __ldg (&wb[(size_t)(i + 2) * NN4_]);
        float4 w3 = __ldg (&wb[(size_t)(i + 3) * NN4_]);

        acc.x += x0.x * w0.x; acc.y += x0.y * w0.y;
        acc.z += x0.z * w0.z; acc.w += x0.w * w0.w;
        acc.x += x1.x * w1.x; acc.y += x1.y * w1.y;
        acc.z += x1.z * w1.z; acc.w += x1.w * w1.w;
        acc.x += x2.x * w2.x; acc.y += x2.y * w2.y;
        acc.z += x2.z * w2.z; acc.w += x2.w * w2.w;
        acc.x += x3.x * w3.x; acc.y += x3.y * w3.y;
        acc.z += x3.z * w3.z; acc.w += x3.w * w3.w;
    }

    red[wid][lane] = acc;
    __syncthreads();

    if (threadIdx.x < 32) {
        float4 sum = red[0][lane];
        #pragma unroll
        for (int k = 1; k < WARPS; ++k) {
            float4 t = red[k][lane];
            sum.x += t.x; sum.y += t.y; sum.z += t.z; sum.w += t.w;
        }

        const int on = b * NN4_ + n4;
        float4 vv = v[on];
        float4 zz = z[on];

        float4 vn;
        vn.x = ALPHA_ * vv.x + sum.x - V_TH_ * zz.x;
        vn.y = ALPHA_ * vv.y + sum.y - V_TH_ * zz.y;
        vn.z = ALPHA_ * vv.z + sum.z - V_TH_ * zz.z;
        vn.w = ALPHA_ * vv.w + sum.w - V_TH_ * zz.w;

        float4 zn;
        zn.x = (vn.x - V_TH_ > 0.f) ? 1.f : 0.f;
        zn.y = (vn.y - V_TH_ > 0.f) ? 1.f : 0.f;
        zn.z = (vn.z - V_TH_ > 0.f) ? 1.f : 0.f;
        zn.w = (vn.w - V_TH_ > 0.f) ? 1.f : 0.f;

        out[on] = vn;                  // v_new: first B*NN floats
        out[B_ * NN4_ + on] = zn;      // z_new: next B*NN floats
    }
}

extern "C" void kernel_launch(void* const* d_in, const int* in_sizes, int n_in,
                              void* d_out, int out_size)
{
    const float4* x = (const float4*)d_in[0];  // [128,1024,512] f32
    const float4* w = (const float4*)d_in[1];  // [1024,512]     f32
    const float4* v = (const float4*)d_in[2];  // [128,512]      f32
    const float4* z = (const float4*)d_in[3];  // [128,512]      f32
    float4* out = (float4*)d_out;              // [2,128,512]    f32

    (void)in_sizes; (void)n_in; (void)out_size;

    lif_kernel<<<B_ * 4, THREADS>>>(x, w, v, z, out);
}